// round 4
// baseline (speedup 1.0000x reference)
#include <cuda_runtime.h>

#define NB    128
#define CIN   8
#define HIN   128
#define WIN   128
#define COUT  64
#define HO    126
#define WO    126
#define PHN   31
#define PWN   31
#define NG    16
#define CPG   4

__device__ float  g_sext[(size_t)NB * COUT * PHN * PWN];   // selected extremum (max or min)
__device__ float2 g_partial[32 * NB * NG];
__device__ float2 g_stats[NB * NG];

// ---------------------------------------------------------------------------
// Pass 1: conv + bias; per-window selected extremum; per-(b,g) partial stats.
// Grid: (32 row-groups, 128 batches, 2 channel-halves), block = 256.
// Thread t: wx = t&31 (4-col window), cb = t>>5 -> channels z*32+cb*4..+3.
// Warp (fixed cb) owns exactly GroupNorm group g = z*8+cb.
// 2-row output blocking: x rows rr..rr+3 loaded to registers once per cin.
// ---------------------------------------------------------------------------
__global__ __launch_bounds__(256, 2) void conv_pass1(const float* __restrict__ x,
                                                     const float* __restrict__ w,
                                                     const float* __restrict__ bias,
                                                     const float* __restrict__ gnw,
                                                     const float* __restrict__ scale)
{
    const int pr = blockIdx.x;          // 0..31
    const int b  = blockIdx.y;
    const int z  = blockIdx.z;          // channel half
    const int t  = threadIdx.x;

    __shared__ float xs[CIN][6][132];   // 6 input rows, 128 cols + 4 zero pad
    __shared__ float wsm[72][32];       // [cin*9+ky*3+kx][cl]
    __shared__ float bsm[32];
    __shared__ unsigned smask;          // bit cl: gnw*scale < 0 -> use min

    // weights for this half: global layout [co][cin][ky][kx]
    for (int i = t; i < 72 * 32; i += 256) {
        int cl = i & 31, k = i >> 5;
        wsm[k][cl] = w[(z * 32 + cl) * 72 + k];
    }
    if (t == 0) smask = 0u;
    __syncthreads();
    if (t < 32) {
        bsm[t] = bias[z * 32 + t];
        if (gnw[z * 32 + t] * scale[z * 32 + t] < 0.f)
            atomicOr(&smask, 1u << t);
    }

    const int h0 = pr * 4;
    for (int i = t; i < CIN * 6 * 32; i += 256) {
        int c4  = i & 31;
        int rr  = (i >> 5) % 6;
        int cin = i / (6 * 32);
        int h   = h0 + rr;
        float4 v = make_float4(0.f, 0.f, 0.f, 0.f);
        if (h < HIN)
            v = *(const float4*)&x[(((size_t)b * CIN + cin) * HIN + h) * WIN + c4 * 4];
        *(float4*)&xs[cin][rr][c4 * 4] = v;
    }
    if (t < CIN * 6) {
        int rr = t % 6, cin = t / 6;
        *(float4*)&xs[cin][rr][128] = make_float4(0.f, 0.f, 0.f, 0.f);
    }
    __syncthreads();

    const int wx   = t & 31;
    const int cb   = t >> 5;
    const int col0 = wx * 4;
    const int R    = (pr == 31) ? 2 : 4;
    const unsigned msk = smask;

    // sel[j]=1 -> negative coefficient, track min; else track max
    float wext[4];
    int   sel[4];
#pragma unroll
    for (int j = 0; j < 4; j++) {
        sel[j]  = (msk >> (cb * 4 + j)) & 1u;
        wext[j] = sel[j] ? 1e30f : -1e30f;
    }
    float s = 0.f, q = 0.f;

#pragma unroll 1
    for (int rr = 0; rr < R; rr += 2) {
        float acc[2][4][4];
#pragma unroll
        for (int r2 = 0; r2 < 2; r2++)
#pragma unroll
            for (int j = 0; j < 4; j++)
#pragma unroll
                for (int c = 0; c < 4; c++) acc[r2][j][c] = 0.f;

#pragma unroll
        for (int cin = 0; cin < CIN; cin++) {
            // load 4 shared x rows rr..rr+3 once
            float xv[4][6];
#pragma unroll
            for (int rx = 0; rx < 4; rx++) {
                const float* xr = &xs[cin][rr + rx][col0];
                float4 xa = *(const float4*)xr;
                float2 xb = *(const float2*)(xr + 4);
                xv[rx][0] = xa.x; xv[rx][1] = xa.y; xv[rx][2] = xa.z;
                xv[rx][3] = xa.w; xv[rx][4] = xb.x; xv[rx][5] = xb.y;
            }
#pragma unroll
            for (int ky = 0; ky < 3; ky++) {
                float4 W0 = *(const float4*)&wsm[cin * 9 + ky * 3 + 0][cb * 4];
                float4 W1 = *(const float4*)&wsm[cin * 9 + ky * 3 + 1][cb * 4];
                float4 W2 = *(const float4*)&wsm[cin * 9 + ky * 3 + 2][cb * 4];
                const float* w0 = (const float*)&W0;
                const float* w1 = (const float*)&W1;
                const float* w2 = (const float*)&W2;
#pragma unroll
                for (int r2 = 0; r2 < 2; r2++) {
                    const float* xq = xv[r2 + ky];
#pragma unroll
                    for (int j = 0; j < 4; j++) {
                        float* a = acc[r2][j];
                        a[0] = fmaf(w0[j], xq[0], fmaf(w1[j], xq[1], fmaf(w2[j], xq[2], a[0])));
                        a[1] = fmaf(w0[j], xq[1], fmaf(w1[j], xq[2], fmaf(w2[j], xq[3], a[1])));
                        a[2] = fmaf(w0[j], xq[2], fmaf(w1[j], xq[3], fmaf(w2[j], xq[4], a[2])));
                        a[3] = fmaf(w0[j], xq[3], fmaf(w1[j], xq[4], fmaf(w2[j], xq[5], a[3])));
                    }
                }
            }
        }

        // epilogue: bias, stats, window extremum for rows rr, rr+1
#pragma unroll
        for (int r2 = 0; r2 < 2; r2++) {
#pragma unroll
            for (int j = 0; j < 4; j++) {
                float bb = bsm[cb * 4 + j];
                float v0 = acc[r2][j][0] + bb, v1 = acc[r2][j][1] + bb;
                float v2 = acc[r2][j][2] + bb, v3 = acc[r2][j][3] + bb;
                if (wx < 31) {
                    s += (v0 + v1) + (v2 + v3);
                    q += (v0 * v0 + v1 * v1) + (v2 * v2 + v3 * v3);
                    if (sel[j])
                        wext[j] = fminf(wext[j], fminf(fminf(v0, v1), fminf(v2, v3)));
                    else
                        wext[j] = fmaxf(wext[j], fmaxf(fmaxf(v0, v1), fmaxf(v2, v3)));
                } else {
                    s += v0 + v1;           // cols 124,125 valid for stats only
                    q += v0 * v0 + v1 * v1;
                }
            }
        }
    }

    // pooled window selected extremum
    if (pr < 31 && wx < 31) {
#pragma unroll
        for (int j = 0; j < 4; j++) {
            int co = z * 32 + cb * 4 + j;
            size_t o = (((size_t)b * COUT + co) * PHN + pr) * PWN + wx;
            g_sext[o] = wext[j];
        }
    }

    // warp-level stats reduction; warp cb exclusively owns group z*8+cb
#pragma unroll
    for (int o = 16; o > 0; o >>= 1) {
        s += __shfl_down_sync(0xffffffffu, s, o);
        q += __shfl_down_sync(0xffffffffu, q, o);
    }
    if (wx == 0)
        g_partial[(pr * NB + b) * NG + z * 8 + cb] = make_float2(s, q);
}

// ---------------------------------------------------------------------------
// Pass 2: fold 32 row-group partials into mean/rstd per (b, g).
// ---------------------------------------------------------------------------
__global__ void stats_pass2()
{
    int idx = blockIdx.x * 256 + threadIdx.x;   // b*16+g
    if (idx >= NB * NG) return;
    float s = 0.f, q = 0.f;
    for (int pr = 0; pr < 32; pr++) {
        float2 p = g_partial[pr * (NB * NG) + idx];
        s += p.x; q += p.y;
    }
    const float inv = 1.f / (float)(CPG * HO * WO);
    float mean = s * inv;
    float var  = q * inv - mean * mean;
    g_stats[idx] = make_float2(mean, rsqrtf(var + 1e-5f));
}

// ---------------------------------------------------------------------------
// Pass 3: per output element, affine-of-extremum + clamp.
// ---------------------------------------------------------------------------
__global__ void apply_pass3(const float* __restrict__ gnw,
                            const float* __restrict__ gnb,
                            const float* __restrict__ scale,
                            float* __restrict__ out, int n)
{
    int idx = blockIdx.x * 256 + threadIdx.x;
    if (idx >= n) return;
    int tmp = idx / PWN;
    tmp /= PHN;
    int c = tmp % COUT;
    int b = tmp / COUT;

    float2 st = g_stats[b * NG + (c >> 2)];
    float gw = gnw[c], sc = scale[c];
    float A  = st.y * gw * sc;
    float Bt = (gnb[c] - st.x * st.y * gw) * sc;

    float v = fmaf(A, g_sext[idx], Bt);
    out[idx] = fminf(fmaxf(v, 0.f), 1.f);
}

// ---------------------------------------------------------------------------
extern "C" void kernel_launch(void* const* d_in, const int* in_sizes, int n_in,
                              void* d_out, int out_size)
{
    const float* x     = (const float*)d_in[0];
    const float* w     = (const float*)d_in[1];
    const float* bias  = (const float*)d_in[2];
    const float* gnw   = (const float*)d_in[3];
    const float* gnb   = (const float*)d_in[4];
    const float* scale = (const float*)d_in[5];
    float* out = (float*)d_out;

    dim3 g1(32, NB, 2);
    conv_pass1<<<g1, 256>>>(x, w, bias, gnw, scale);
    stats_pass2<<<(NB * NG + 255) / 256, 256>>>();
    int n = NB * COUT * PHN * PWN;
    apply_pass3<<<(n + 255) / 256, 256>>>(gnw, gnb, scale, out, n);
}

// round 5
// speedup vs baseline: 3.7859x; 3.7859x over previous
#include <cuda_runtime.h>

#define NB    128
#define CIN   8
#define HIN   128
#define WIN   128
#define COUT  64
#define HO    126
#define WO    126
#define PHN   31
#define PWN   31
#define NG    16
#define CPG   4

__device__ float  g_sext[(size_t)NB * COUT * PHN * PWN];   // max of sign-adjusted conv over window
__device__ float2 g_partial[32 * NB * NG];
__device__ float2 g_stats[NB * NG];

// ---------------------------------------------------------------------------
// Pass 1: conv + bias; per-window sign-adjusted max; per-(b,g) partial stats.
// Grid: (32 row-groups, 128 batches, 2 channel-halves), block = 256.
// Thread t: wx = t&31 (4-col window), cb = t>>5 -> channels z*32+cb*4..+3.
// Warp (fixed cb) owns exactly GroupNorm group g = z*8+cb.
// cin loop NOT unrolled -> small live set, no spills.
// ---------------------------------------------------------------------------
__global__ __launch_bounds__(256, 2) void conv_pass1(const float* __restrict__ x,
                                                     const float* __restrict__ w,
                                                     const float* __restrict__ bias,
                                                     const float* __restrict__ gnw,
                                                     const float* __restrict__ scale)
{
    const int pr = blockIdx.x;          // 0..31
    const int b  = blockIdx.y;
    const int z  = blockIdx.z;          // channel half
    const int t  = threadIdx.x;

    __shared__ float xs[CIN][6][132];   // 6 input rows, 128 cols + 4 zero pad
    __shared__ float wsm[72][32];       // [cin*9+ky*3+kx][cl]
    __shared__ float bsm[32];
    __shared__ float sgsm[32];          // +1 / -1 per channel

    // weights for this half: global layout [co][cin][ky][kx]
    for (int i = t; i < 72 * 32; i += 256) {
        int cl = i & 31, k = i >> 5;
        wsm[k][cl] = w[(z * 32 + cl) * 72 + k];
    }
    if (t < 32) {
        bsm[t]  = bias[z * 32 + t];
        sgsm[t] = (gnw[z * 32 + t] * scale[z * 32 + t] < 0.f) ? -1.f : 1.f;
    }

    const int h0 = pr * 4;
    for (int i = t; i < CIN * 6 * 32; i += 256) {
        int c4  = i & 31;
        int rr  = (i >> 5) % 6;
        int cin = i / (6 * 32);
        int h   = h0 + rr;
        float4 v = make_float4(0.f, 0.f, 0.f, 0.f);
        if (h < HIN)
            v = *(const float4*)&x[(((size_t)b * CIN + cin) * HIN + h) * WIN + c4 * 4];
        *(float4*)&xs[cin][rr][c4 * 4] = v;
    }
    if (t < CIN * 6) {
        int rr = t % 6, cin = t / 6;
        *(float4*)&xs[cin][rr][128] = make_float4(0.f, 0.f, 0.f, 0.f);
    }
    __syncthreads();

    const int wx   = t & 31;
    const int cb   = t >> 5;
    const int col0 = wx * 4;
    const int R    = (pr == 31) ? 2 : 4;

    float wext[4], sg[4];
#pragma unroll
    for (int j = 0; j < 4; j++) {
        sg[j]   = sgsm[cb * 4 + j];
        wext[j] = -1e30f;
    }
    float s = 0.f, q = 0.f;

#pragma unroll 1
    for (int r = 0; r < R; r++) {
        float acc[4][4];
#pragma unroll
        for (int j = 0; j < 4; j++)
#pragma unroll
            for (int c = 0; c < 4; c++) acc[j][c] = 0.f;

#pragma unroll 1
        for (int cin = 0; cin < CIN; cin++) {
#pragma unroll
            for (int ky = 0; ky < 3; ky++) {
                const float* xr = &xs[cin][r + ky][col0];
                float4 xa = *(const float4*)xr;
                float2 xb = *(const float2*)(xr + 4);
                float xv0 = xa.x, xv1 = xa.y, xv2 = xa.z;
                float xv3 = xa.w, xv4 = xb.x, xv5 = xb.y;
                float4 W0 = *(const float4*)&wsm[cin * 9 + ky * 3 + 0][cb * 4];
                float4 W1 = *(const float4*)&wsm[cin * 9 + ky * 3 + 1][cb * 4];
                float4 W2 = *(const float4*)&wsm[cin * 9 + ky * 3 + 2][cb * 4];
                const float* w0 = (const float*)&W0;
                const float* w1 = (const float*)&W1;
                const float* w2 = (const float*)&W2;
#pragma unroll
                for (int j = 0; j < 4; j++) {
                    acc[j][0] = fmaf(w0[j], xv0, fmaf(w1[j], xv1, fmaf(w2[j], xv2, acc[j][0])));
                    acc[j][1] = fmaf(w0[j], xv1, fmaf(w1[j], xv2, fmaf(w2[j], xv3, acc[j][1])));
                    acc[j][2] = fmaf(w0[j], xv2, fmaf(w1[j], xv3, fmaf(w2[j], xv4, acc[j][2])));
                    acc[j][3] = fmaf(w0[j], xv3, fmaf(w1[j], xv4, fmaf(w2[j], xv5, acc[j][3])));
                }
            }
        }

        // epilogue: bias, stats, sign-adjusted window max
#pragma unroll
        for (int j = 0; j < 4; j++) {
            float bb = bsm[cb * 4 + j];
            float v0 = acc[j][0] + bb, v1 = acc[j][1] + bb;
            float v2 = acc[j][2] + bb, v3 = acc[j][3] + bb;
            if (wx < 31) {
                s += (v0 + v1) + (v2 + v3);
                q += (v0 * v0 + v1 * v1) + (v2 * v2 + v3 * v3);
                float g0 = sg[j] * v0, g1 = sg[j] * v1;
                float g2 = sg[j] * v2, g3 = sg[j] * v3;
                wext[j] = fmaxf(wext[j], fmaxf(fmaxf(g0, g1), fmaxf(g2, g3)));
            } else {
                s += v0 + v1;               // cols 124,125 valid for stats only
                q += v0 * v0 + v1 * v1;
            }
        }
    }

    // pooled window sign-adjusted max
    if (pr < 31 && wx < 31) {
#pragma unroll
        for (int j = 0; j < 4; j++) {
            int co = z * 32 + cb * 4 + j;
            size_t o = (((size_t)b * COUT + co) * PHN + pr) * PWN + wx;
            g_sext[o] = wext[j];
        }
    }

    // warp-level stats reduction; warp cb exclusively owns group z*8+cb
#pragma unroll
    for (int o = 16; o > 0; o >>= 1) {
        s += __shfl_down_sync(0xffffffffu, s, o);
        q += __shfl_down_sync(0xffffffffu, q, o);
    }
    if (wx == 0)
        g_partial[(pr * NB + b) * NG + z * 8 + cb] = make_float2(s, q);
}

// ---------------------------------------------------------------------------
// Pass 2: fold 32 row-group partials into mean/rstd per (b, g).
// ---------------------------------------------------------------------------
__global__ void stats_pass2()
{
    int idx = blockIdx.x * 256 + threadIdx.x;   // b*16+g
    if (idx >= NB * NG) return;
    float s = 0.f, q = 0.f;
    for (int pr = 0; pr < 32; pr++) {
        float2 p = g_partial[pr * (NB * NG) + idx];
        s += p.x; q += p.y;
    }
    const float inv = 1.f / (float)(CPG * HO * WO);
    float mean = s * inv;
    float var  = q * inv - mean * mean;
    g_stats[idx] = make_float2(mean, rsqrtf(var + 1e-5f));
}

// ---------------------------------------------------------------------------
// Pass 3: v = |A| * ext + B, clamp.  (ext = max of sign(A)-adjusted conv)
// ---------------------------------------------------------------------------
__global__ void apply_pass3(const float* __restrict__ gnw,
                            const float* __restrict__ gnb,
                            const float* __restrict__ scale,
                            float* __restrict__ out, int n)
{
    int idx = blockIdx.x * 256 + threadIdx.x;
    if (idx >= n) return;
    int tmp = idx / PWN;
    tmp /= PHN;
    int c = tmp % COUT;
    int b = tmp / COUT;

    float2 st = g_stats[b * NG + (c >> 2)];
    float gw = gnw[c], sc = scale[c];
    float A  = st.y * gw * sc;
    float Bt = (gnb[c] - st.x * st.y * gw) * sc;

    float v = fmaf(fabsf(A), g_sext[idx], Bt);
    out[idx] = fminf(fmaxf(v, 0.f), 1.f);
}

// ---------------------------------------------------------------------------
extern "C" void kernel_launch(void* const* d_in, const int* in_sizes, int n_in,
                              void* d_out, int out_size)
{
    const float* x     = (const float*)d_in[0];
    const float* w     = (const float*)d_in[1];
    const float* bias  = (const float*)d_in[2];
    const float* gnw   = (const float*)d_in[3];
    const float* gnb   = (const float*)d_in[4];
    const float* scale = (const float*)d_in[5];
    float* out = (float*)d_out;

    dim3 g1(32, NB, 2);
    conv_pass1<<<g1, 256>>>(x, w, bias, gnw, scale);
    stats_pass2<<<(NB * NG + 255) / 256, 256>>>();
    int n = NB * COUT * PHN * PWN;
    apply_pass3<<<(n + 255) / 256, 256>>>(gnw, gnb, scale, out, n);
}